// round 6
// baseline (speedup 1.0000x reference)
#include <cuda_runtime.h>
#include <math.h>

#define BATCH 128
#define NSP   14
#define HW    196
#define KC    512
#define NCLS  10
#define SFEAT (BATCH*HW*KC)   // 12845056

// ---------------- scratch (device globals; no allocation allowed) ----------
__device__ float g_x3[SFEAT];          // relu(conv + b), 51.4 MB
__device__ int   g_arg1[BATCH*KC];
__device__ int   g_arg2[BATCH*KC];
__device__ float g_mean1[BATCH*KC];
__device__ float g_mean2[BATCH*KC];
__device__ int   g_fcls1[KC];
__device__ int   g_fcls2[KC];
__device__ float g_logit[BATCH*2*NCLS]; // dense partials: [b][half][k], no atomics

// t_p[i,j,a,b] = tao * max(1 - beta*(|a-i|+|b-j|)/n, -1), computed inline
__device__ __forceinline__ float tpl_val(int pi, int pj, int i, int j) {
    int di = i - pi; if (di < 0) di = -di;
    int dj = j - pj; if (dj < 0) dj = -dj;
    float d = (float)(di + dj);
    float v = 1.0f - (2.0f * d) / 14.0f;
    v = fmaxf(v, -1.0f);
    const float TAO = 0.5f / 196.0f;
    return TAO * v;
}

// ---------------- stage 1: masked_output on inputs --------------------------
// grid = (BATCH, 2), block = 256 threads; thread handles channel c.
__global__ __launch_bounds__(256) void masked1_kernel(
        const float* __restrict__ in,
        float* __restrict__ x1o,
        float* __restrict__ posto,
        float* __restrict__ rawo) {
    const int b = blockIdx.x;
    const int c = blockIdx.y * 256 + threadIdx.x;
    const size_t base = (size_t)b * HW * KC + c;
    float best = -3.402823e38f; int bi = 0;
    #pragma unroll 4
    for (int p = 0; p < HW; ++p) {
        float v = in[base + (size_t)p * KC];
        if (v > best) { best = v; bi = p; }      // strict > == first-max
    }
    g_arg1[b * KC + c] = bi;
    const int pi = bi / 14, pj = bi - pi * 14;
    float s = 0.f;
    #pragma unroll 2
    for (int p = 0; p < HW; ++p) {
        const int i = p / 14, j = p - i * 14;
        const float t = tpl_val(pi, pj, i, j);
        const float v = in[base + (size_t)p * KC];
        const float m = fmaxf(v * t, 0.f);
        s += m;
        x1o[base + (size_t)p * KC]   = m;
        posto[base + (size_t)p * KC] = t;
        rawo[base + (size_t)p * KC]  = v;
    }
    g_mean1[b * KC + c] = s / 196.0f;
}

// ---------------- stage 2: 3x3 SAME conv as implicit GEMM (fp32) ------------
// C[m,n] = sum_k A[m,k]*W[k,n];  m=(b,oh,ow) (25088), n=co (512), k=tap*512+ci
#define BK 8
#define KT (4608 / BK)   // 576

#define CONV_LOADG(KTIDX)                                                        \
    {                                                                            \
        int k = (KTIDX) * BK + a_kc;                                             \
        int tap = k >> 9;                                                        \
        int ci  = k & 511;                                                       \
        int kh = tap / 3, kw = tap - kh * 3;                                     \
        int ih = oh + kh - 1, iw = ow + kw - 1;                                  \
        if ((unsigned)ih < 14u && (unsigned)iw < 14u)                            \
            ar = *reinterpret_cast<const float4*>(                               \
                x1 + (((size_t)bb * HW + ih * 14 + iw) << 9) + ci);              \
        else { ar.x = 0.f; ar.y = 0.f; ar.z = 0.f; ar.w = 0.f; }                 \
        int kB = (KTIDX) * BK + b_kr;                                            \
        br = *reinterpret_cast<const float4*>(w + ((size_t)kB << 9) + n0 + b_nc);\
    }

#define CONV_STORE_SMEM(BUF)                                                     \
    {                                                                            \
        As[BUF][a_kc + 0][a_row] = ar.x;                                         \
        As[BUF][a_kc + 1][a_row] = ar.y;                                         \
        As[BUF][a_kc + 2][a_row] = ar.z;                                         \
        As[BUF][a_kc + 3][a_row] = ar.w;                                         \
        *reinterpret_cast<float4*>(&Bs[BUF][b_kr][b_nc]) = br;                   \
    }

__global__ __launch_bounds__(256) void conv_kernel(const float* __restrict__ x1,
                                                   const float* __restrict__ w,
                                                   const float* __restrict__ bias) {
    __shared__ __align__(16) float As[2][BK][128];
    __shared__ __align__(16) float Bs[2][BK][128];
    const int tid = threadIdx.x;
    const int n0 = blockIdx.x * 128;   // 0..3
    const int m0 = blockIdx.y * 128;   // 0..195

    const int a_row = tid >> 1;            // 0..127
    const int a_kc  = (tid & 1) << 2;      // 0 or 4
    const int b_kr  = tid >> 5;            // 0..7
    const int b_nc  = (tid & 31) << 2;     // 0..124

    const int m  = m0 + a_row;
    const int bb = m / HW;
    const int pp = m - bb * HW;
    const int oh = pp / 14;
    const int ow = pp - oh * 14;

    const int tx = tid & 15, ty = tid >> 4;

    float acc[8][8];
    #pragma unroll
    for (int i = 0; i < 8; ++i)
        #pragma unroll
        for (int j = 0; j < 8; ++j) acc[i][j] = 0.f;

    float4 ar, br;
    CONV_LOADG(0);
    CONV_STORE_SMEM(0);
    __syncthreads();

    int cur = 0;
    for (int kt = 0; kt < KT; ++kt) {
        const bool has = (kt + 1 < KT);
        if (has) CONV_LOADG(kt + 1);
        #pragma unroll
        for (int kk = 0; kk < BK; ++kk) {
            float4 a0 = *reinterpret_cast<const float4*>(&As[cur][kk][ty * 8]);
            float4 a1 = *reinterpret_cast<const float4*>(&As[cur][kk][ty * 8 + 4]);
            float4 b0 = *reinterpret_cast<const float4*>(&Bs[cur][kk][tx * 8]);
            float4 b1 = *reinterpret_cast<const float4*>(&Bs[cur][kk][tx * 8 + 4]);
            float av[8] = {a0.x, a0.y, a0.z, a0.w, a1.x, a1.y, a1.z, a1.w};
            float bv[8] = {b0.x, b0.y, b0.z, b0.w, b1.x, b1.y, b1.z, b1.w};
            #pragma unroll
            for (int i = 0; i < 8; ++i)
                #pragma unroll
                for (int j = 0; j < 8; ++j)
                    acc[i][j] = fmaf(av[i], bv[j], acc[i][j]);
        }
        if (has) {
            const int nb = cur ^ 1;
            CONV_STORE_SMEM(nb);
            __syncthreads();
            cur = nb;
        }
    }

    // epilogue: + bias, relu, write g_x3.  M,N tile exactly -> no bounds checks
    #pragma unroll
    for (int i = 0; i < 8; ++i) {
        const int mm = m0 + ty * 8 + i;
        const size_t rb = (size_t)mm << 9;
        #pragma unroll
        for (int j = 0; j < 8; ++j) {
            const int nn = n0 + tx * 8 + j;
            g_x3[rb + nn] = fmaxf(acc[i][j] + bias[nn], 0.f);
        }
    }
}

// ---------------- stage 3: masked_output on x3 -------------------------------
__global__ __launch_bounds__(256) void masked2_kernel(float* __restrict__ x2o) {
    const int b = blockIdx.x;
    const int c = blockIdx.y * 256 + threadIdx.x;
    const size_t base = (size_t)b * HW * KC + c;
    float best = -3.402823e38f; int bi = 0;
    #pragma unroll 4
    for (int p = 0; p < HW; ++p) {
        float v = g_x3[base + (size_t)p * KC];
        if (v > best) { best = v; bi = p; }
    }
    g_arg2[b * KC + c] = bi;
    const int pi = bi / 14, pj = bi - pi * 14;
    float s = 0.f;
    #pragma unroll 2
    for (int p = 0; p < HW; ++p) {
        const int i = p / 14, j = p - i * 14;
        const float t = tpl_val(pi, pj, i, j);
        const float v = g_x3[base + (size_t)p * KC];
        const float m = fmaxf(v * t, 0.f);
        s += m;
        x2o[base + (size_t)p * KC] = m;
    }
    g_mean2[b * KC + c] = s / 196.0f;
}

// ---------------- stage 4: per-channel class stats (both layers) -------------
// grid = 2 (channel halves), block = 256 threads; thread handles channel c.
__global__ __launch_bounds__(256) void stats_kernel(
        const int* __restrict__ gt,
        const float* __restrict__ as1, const float* __restrict__ cs1,
        const float* __restrict__ as2, const float* __restrict__ cs2) {
    __shared__ int   s_gt[BATCH];
    __shared__ float s_cls1[NCLS], s_cls2[NCLS];
    const int tid = threadIdx.x;
    const int c = blockIdx.x * 256 + tid;
    if (tid < BATCH) s_gt[tid] = gt[tid];
    __syncthreads();
    if (tid == 0) {
        float cnt[NCLS];
        for (int k = 0; k < NCLS; ++k) cnt[k] = 0.f;
        for (int b = 0; b < BATCH; ++b) cnt[s_gt[b]] += 1.0f;
        for (int k = 0; k < NCLS; ++k) {
            s_cls1[k] = cs1[k] + cnt[k];
            s_cls2[k] = cs2[k] + cnt[k];
        }
    }
    __syncthreads();

    // layer 1
    {
        float act[NCLS];
        #pragma unroll
        for (int k = 0; k < NCLS; ++k) act[k] = 0.f;
        for (int b = 0; b < BATCH; ++b) act[s_gt[b]] += g_mean1[b * KC + c];
        int bestk = 0; float bestv = -3.402823e38f;
        #pragma unroll
        for (int k = 0; k < NCLS; ++k) {
            const float cn = s_cls1[k];
            const float fm = (cn == 0.f) ? 0.f : (as1[c * NCLS + k] + act[k]) / cn;
            if (fm > bestv) { bestv = fm; bestk = k; }   // first-max
        }
        g_fcls1[c] = bestk;
    }
    // layer 2
    {
        float act[NCLS];
        #pragma unroll
        for (int k = 0; k < NCLS; ++k) act[k] = 0.f;
        for (int b = 0; b < BATCH; ++b) act[s_gt[b]] += g_mean2[b * KC + c];
        int bestk = 0; float bestv = -3.402823e38f;
        #pragma unroll
        for (int k = 0; k < NCLS; ++k) {
            const float cn = s_cls2[k];
            const float fm = (cn == 0.f) ? 0.f : (as2[c * NCLS + k] + act[k]) / cn;
            if (fm > bestv) { bestv = fm; bestk = k; }
        }
        g_fcls2[c] = bestk;
    }
}

// ---------------- stage 5: loss tensors --------------------------------------
// loss[b,h,w,c] = (fclass[c]==gt[b]) ? relu(t_p[pi,pj,h,w]) : 0
// grid = (BATCH*HW, 2), block = 256.
__global__ __launch_bounds__(256) void loss_kernel(const int* __restrict__ gt,
                                                   float* __restrict__ l1,
                                                   float* __restrict__ l2) {
    const int bp = blockIdx.x;           // b*196 + p
    const int b = bp / HW;
    const int p = bp - b * HW;
    const int i = p / 14, j = p - (p / 14) * 14;
    const int c = blockIdx.y * 256 + threadIdx.x;
    const int gtb = gt[b];
    const size_t o = (size_t)bp * KC + c;

    float v1 = 0.f;
    if (g_fcls1[c] == gtb) {
        const int a = g_arg1[b * KC + c];
        const int pi = a / 14, pj = a - (a / 14) * 14;
        v1 = fmaxf(tpl_val(pi, pj, i, j), 0.f);
    }
    l1[o] = v1;

    float v2 = 0.f;
    if (g_fcls2[c] == gtb) {
        const int a = g_arg2[b * KC + c];
        const int pi = a / 14, pj = a - (a / 14) * 14;
        v2 = fmaxf(tpl_val(pi, pj, i, j), 0.f);
    }
    l2[o] = v2;
}

// ---------------- stage 6a: maxpool 2x2 + dense (partial) --------------------
// grid = BATCH * 2; each half-block covers half the D dimension.
// Partials stored to distinct slots -> no atomics, no pre-zeroing needed.
__global__ __launch_bounds__(256) void dense_kernel(const float* __restrict__ x2,
                                                    const float* __restrict__ dw) {
    const int b    = blockIdx.x >> 1;
    const int half = blockIdx.x & 1;
    const int tid  = threadIdx.x;   // 256
    const float* xb = x2 + (size_t)b * HW * KC;
    float acc[NCLS];
    #pragma unroll
    for (int k = 0; k < NCLS; ++k) acc[k] = 0.f;

    const int D = 7 * 7 * KC;            // 25088
    const int d0 = half * (D / 2);
    for (int d = d0 + tid; d < d0 + D / 2; d += 256) {
        const int c  = d & 511;
        const int pw = (d >> 9) % 7;
        const int ph = d / (KC * 7);
        const float* p00 = xb + ((size_t)((2 * ph) * 14 + 2 * pw)) * KC + c;
        const float m = fmaxf(fmaxf(p00[0], p00[KC]),
                              fmaxf(p00[14 * KC], p00[15 * KC]));
        const float* wr = dw + (size_t)d * NCLS;
        #pragma unroll
        for (int k = 0; k < NCLS; ++k) acc[k] = fmaf(m, wr[k], acc[k]);
    }

    __shared__ float sacc[NCLS];
    if (tid < NCLS) sacc[tid] = 0.f;
    __syncthreads();
    #pragma unroll
    for (int k = 0; k < NCLS; ++k) {
        float v = acc[k];
        for (int off = 16; off; off >>= 1) v += __shfl_down_sync(0xffffffffu, v, off);
        if ((tid & 31) == 0) atomicAdd(&sacc[k], v);   // smem atomics only
    }
    __syncthreads();
    if (tid < NCLS) g_logit[(b * 2 + half) * NCLS + tid] = sacc[tid];
}

// ---------------- stage 6b: combine partials + softmax ------------------------
__global__ __launch_bounds__(32) void softmax_kernel(const float* __restrict__ db,
                                                     float* __restrict__ probs) {
    const int b = blockIdx.x;
    if (threadIdx.x == 0) {
        float lg[NCLS];
        float mx = -3.402823e38f;
        for (int k = 0; k < NCLS; ++k) {
            lg[k] = g_logit[(b * 2 + 0) * NCLS + k]
                  + g_logit[(b * 2 + 1) * NCLS + k] + db[k];
            mx = fmaxf(mx, lg[k]);
        }
        float s = 0.f;
        for (int k = 0; k < NCLS; ++k) { lg[k] = expf(lg[k] - mx); s += lg[k]; }
        for (int k = 0; k < NCLS; ++k) probs[b * NCLS + k] = lg[k] / s;
    }
}

// ---------------- launch ------------------------------------------------------
extern "C" void kernel_launch(void* const* d_in, const int* in_sizes, int n_in,
                              void* d_out, int out_size) {
    const float* inp     = (const float*)d_in[0];
    const int*   gt      = (const int*)  d_in[1];
    const float* conv_w  = (const float*)d_in[2];
    const float* conv_b  = (const float*)d_in[3];
    const float* dense_w = (const float*)d_in[4];
    const float* dense_b = (const float*)d_in[5];
    const float* as1     = (const float*)d_in[6];
    const float* as2     = (const float*)d_in[7];
    const float* cs1     = (const float*)d_in[8];
    const float* cs2     = (const float*)d_in[9];

    float* out   = (float*)d_out;
    float* probs = out;                    // [128,10]
    float* x1    = probs + BATCH * NCLS;   // [128,14,14,512]
    float* x2    = x1 + SFEAT;
    float* loss1 = x2 + SFEAT;
    float* loss2 = loss1 + SFEAT;
    float* raw   = loss2 + SFEAT;
    float* post1 = raw + SFEAT;

    masked1_kernel<<<dim3(BATCH, 2), 256>>>(inp, x1, post1, raw);
    conv_kernel<<<dim3(4, 196), 256>>>(x1, conv_w, conv_b);
    masked2_kernel<<<dim3(BATCH, 2), 256>>>(x2);
    stats_kernel<<<2, 256>>>(gt, as1, cs1, as2, cs2);
    loss_kernel<<<dim3(BATCH * HW, 2), 256>>>(gt, loss1, loss2);
    dense_kernel<<<BATCH * 2, 256>>>(x2, dense_w);
    softmax_kernel<<<BATCH, 32>>>(dense_b, probs);
}